// round 13
// baseline (speedup 1.0000x reference)
#include <cuda_runtime.h>
#include <cstdint>

#define N_ROWS  32768
#define D_DIM   512
#define K_CODES 4096
#define EPSF    1e-6f
#define MARGIN  0.15f

// ---- GEMM tiling (int8: BK=128 elems = 128B rows, same byte layout) ----
#define BM 128
#define BN 256
#define BK 128
#define NKT (D_DIM / BK)      // 4 depth tiles
#define NKC (K_CODES / BN)    // 16 code chunks
#define NSTAGE 4

// smem layout (dynamic): A 4x16KB | B 4x32KB | enorm 1KB
#define SA_OFF 0
#define SB_OFF 65536
#define SE_OFF 196608
#define SMEMSZ 197632

// ---- scratch (static, no allocations) ----
__device__ __align__(16) int8_t g_xq[N_ROWS * D_DIM];
__device__ __align__(16) int8_t g_eq[K_CODES * D_DIM];
__device__ unsigned g_maxbits[2];      // max|x|, max|e| as float bits
__device__ float g_quant[3];           // inv_sx, inv_se, prod = 2*sx*se
__device__ float g_enorm[K_CODES];
__device__ float g_xnorm[N_ROWS];
__device__ float g_cand_v[N_ROWS * 4];
__device__ int   g_cand_i[N_ROWS * 4];
__device__ float g_embed_sum[K_CODES * D_DIM];
__device__ float g_counts[K_CODES];
__device__ float g_total;

// ---------------------------------------------------------------------------
// helpers
// ---------------------------------------------------------------------------
__device__ __forceinline__ uint32_t smem_u32(const void* p) {
    uint32_t a;
    asm("{ .reg .u64 t; cvta.to.shared.u64 t, %1; cvt.u32.u64 %0, t; }"
        : "=r"(a) : "l"(p));
    return a;
}

__device__ __forceinline__ void ldsm_x4(uint32_t a, uint32_t& r0, uint32_t& r1,
                                        uint32_t& r2, uint32_t& r3) {
    asm volatile("ldmatrix.sync.aligned.m8n8.x4.shared.b16 {%0,%1,%2,%3}, [%4];"
                 : "=r"(r0), "=r"(r1), "=r"(r2), "=r"(r3) : "r"(a));
}

__device__ __forceinline__ void mma_s8(int* c, const uint32_t* a,
                                       uint32_t b0, uint32_t b1) {
    asm volatile(
        "mma.sync.aligned.m16n8k32.row.col.s32.s8.s8.s32 "
        "{%0,%1,%2,%3}, {%4,%5,%6,%7}, {%8,%9}, {%0,%1,%2,%3};"
        : "+r"(c[0]), "+r"(c[1]), "+r"(c[2]), "+r"(c[3])
        : "r"(a[0]), "r"(a[1]), "r"(a[2]), "r"(a[3]), "r"(b0), "r"(b1));
}

__device__ __forceinline__ void top4_insert(float s, int k, float v[4], int id[4]) {
    if (s < v[3]) {
        if (s < v[1]) {
            v[3] = v[2]; id[3] = id[2]; v[2] = v[1]; id[2] = id[1];
            if (s < v[0]) { v[1] = v[0]; id[1] = id[0]; v[0] = s; id[0] = k; }
            else          { v[1] = s; id[1] = k; }
        } else {
            if (s < v[2]) { v[3] = v[2]; id[3] = id[2]; v[2] = s; id[2] = k; }
            else          { v[3] = s; id[3] = k; }
        }
    }
}

// ---------------------------------------------------------------------------
// 0) zero scratch
// ---------------------------------------------------------------------------
__global__ void zero_kernel() {
    int i = blockIdx.x * blockDim.x + threadIdx.x;
    int stride = gridDim.x * blockDim.x;
    for (int j = i; j < K_CODES * D_DIM; j += stride) g_embed_sum[j] = 0.f;
    if (i < K_CODES) g_counts[i] = 0.f;
    if (i == 0) { g_total = 0.f; g_maxbits[0] = 0u; g_maxbits[1] = 0u; }
}

// ---------------------------------------------------------------------------
// 1) exact norms, reference rounding order (sequential mul/add)
// ---------------------------------------------------------------------------
__global__ void enorm_kernel(const float* __restrict__ embed) {
    int k = blockIdx.x * blockDim.x + threadIdx.x;
    if (k >= K_CODES) return;
    const float4* row = reinterpret_cast<const float4*>(&embed[(size_t)k * D_DIM]);
    float s = 0.f;
#pragma unroll 8
    for (int i = 0; i < D_DIM / 4; i++) {
        float4 v = row[i];
        s = __fadd_rn(s, __fmul_rn(v.x, v.x));
        s = __fadd_rn(s, __fmul_rn(v.y, v.y));
        s = __fadd_rn(s, __fmul_rn(v.z, v.z));
        s = __fadd_rn(s, __fmul_rn(v.w, v.w));
    }
    g_enorm[k] = s;
}
__global__ void xnorm_kernel(const float* __restrict__ x) {
    int n = blockIdx.x * blockDim.x + threadIdx.x;
    if (n >= N_ROWS) return;
    const float4* row = reinterpret_cast<const float4*>(&x[(size_t)n * D_DIM]);
    float s = 0.f;
#pragma unroll 8
    for (int i = 0; i < D_DIM / 4; i++) {
        float4 v = row[i];
        s = __fadd_rn(s, __fmul_rn(v.x, v.x));
        s = __fadd_rn(s, __fmul_rn(v.y, v.y));
        s = __fadd_rn(s, __fmul_rn(v.z, v.z));
        s = __fadd_rn(s, __fmul_rn(v.w, v.w));
    }
    g_xnorm[n] = s;
}

// ---------------------------------------------------------------------------
// 2) max-abs reduction (deterministic via uint atomicMax), scales, quantize
// ---------------------------------------------------------------------------
__global__ void maxabs_kernel(const float* __restrict__ src, int n4, int slot) {
    int i = blockIdx.x * blockDim.x + threadIdx.x;
    int stride = gridDim.x * blockDim.x;
    float m = 0.f;
    for (int j = i; j < n4; j += stride) {
        float4 v = reinterpret_cast<const float4*>(src)[j];
        m = fmaxf(m, fmaxf(fmaxf(fabsf(v.x), fabsf(v.y)),
                           fmaxf(fabsf(v.z), fabsf(v.w))));
    }
#pragma unroll
    for (int o = 16; o > 0; o >>= 1)
        m = fmaxf(m, __shfl_down_sync(0xffffffffu, m, o));
    if ((threadIdx.x & 31) == 0)
        atomicMax(&g_maxbits[slot], __float_as_uint(m));
}

__global__ void scale_kernel() {
    float mx = __uint_as_float(g_maxbits[0]);
    float me = __uint_as_float(g_maxbits[1]);
    float sx = mx / 127.0f, se = me / 127.0f;
    g_quant[0] = 127.0f / mx;
    g_quant[1] = 127.0f / me;
    g_quant[2] = 2.0f * sx * se;
}

__global__ void quant_kernel(const float* __restrict__ src,
                             int8_t* __restrict__ dst, int n4, int slot) {
    int i = blockIdx.x * blockDim.x + threadIdx.x;
    if (i >= n4) return;
    float inv = g_quant[slot];
    float4 v = reinterpret_cast<const float4*>(src)[i];
    int b0 = __float2int_rn(v.x * inv);
    int b1 = __float2int_rn(v.y * inv);
    int b2 = __float2int_rn(v.z * inv);
    int b3 = __float2int_rn(v.w * inv);
    uint32_t p = (uint32_t)(b0 & 0xff) | ((uint32_t)(b1 & 0xff) << 8) |
                 ((uint32_t)(b2 & 0xff) << 16) | ((uint32_t)(b3 & 0xff) << 24);
    reinterpret_cast<uint32_t*>(dst)[i] = p;
}

// ---------------------------------------------------------------------------
// 3) int8 mma.sync GEMM + per-row top-4 approximate candidates
//    score(n,k) = enorm_k - 2*sx*se * <xq_n, eq_k>
// ---------------------------------------------------------------------------
__device__ __forceinline__ void load_tile(uint32_t sb,
                                          const int8_t* __restrict__ xq,
                                          const int8_t* __restrict__ eq,
                                          int rowBase, int kc, int kt,
                                          int stage, int tid) {
    const uint32_t aOff = sb + SA_OFF + stage * 16384;
    const uint32_t bOff = sb + SB_OFF + stage * 32768;
    // A: 128 rows x 8 16B-chunks = 1024 transfers (2/thread)
#pragma unroll
    for (int i = 0; i < 2; i++) {
        int idx = tid + i * 512;
        int r = idx >> 3, c = idx & 7;
        uint32_t sw = (uint32_t)(r * 128 + ((c ^ (r & 7)) << 4));
        const int8_t* ga = xq + (size_t)(rowBase + r) * D_DIM + kt * BK + c * 16;
        asm volatile("cp.async.cg.shared.global [%0], [%1], 16;"
                     :: "r"(aOff + sw), "l"(ga));
    }
    // B: 256 rows x 8 16B-chunks = 2048 transfers (4/thread)
#pragma unroll
    for (int i = 0; i < 4; i++) {
        int idx = tid + i * 512;
        int r = idx >> 3, c = idx & 7;
        uint32_t sw = (uint32_t)(r * 128 + ((c ^ (r & 7)) << 4));
        const int8_t* gb = eq + (size_t)(kc * BN + r) * D_DIM + kt * BK + c * 16;
        asm volatile("cp.async.cg.shared.global [%0], [%1], 16;"
                     :: "r"(bOff + sw), "l"(gb));
    }
    asm volatile("cp.async.commit_group;" ::: "memory");
}

__global__ __launch_bounds__(512, 1) void gemm_topk_kernel(
    const int8_t* __restrict__ xq, const int8_t* __restrict__ eq) {
    extern __shared__ char sm[];
    const uint32_t sb = smem_u32(sm);
    const int tid = threadIdx.x, lane = tid & 31, wid = tid >> 5;
    const int warpM = wid & 3;           // 4 row-groups of 32
    const int warpN = wid >> 2;          // 4 col-quarters of 64
    const int rowBase = blockIdx.x * BM;
    const float prod = g_quant[2];

    float tv[4][4]; int ti4[4][4];
#pragma unroll
    for (int s = 0; s < 4; s++)
#pragma unroll
        for (int j = 0; j < 4; j++) { tv[s][j] = 3.4e38f; ti4[s][j] = 0x7fffffff; }

    // ldmatrix address components (identical byte layout to verified bf16;
    // chunks are now 16-int8 k-halves of k32)
    const int aRow0 = warpM * 32 + (lane & 15);
    const int aCsel = lane >> 4;
    const int bRow0 = warpN * 64 + ((lane >> 4) << 3) + (lane & 7);
    const int bCsel = (lane >> 3) & 1;

    for (int kc = 0; kc < NKC; kc++) {
        if (tid < BN)
            reinterpret_cast<float*>(sm + SE_OFF)[tid] = g_enorm[kc * BN + tid];

        int acc[2][8][4];
#pragma unroll
        for (int mf = 0; mf < 2; mf++)
#pragma unroll
            for (int nf = 0; nf < 8; nf++)
#pragma unroll
                for (int e = 0; e < 4; e++) acc[mf][nf][e] = 0;

        load_tile(sb, xq, eq, rowBase, kc, 0, 0, tid);
        load_tile(sb, xq, eq, rowBase, kc, 1, 1, tid);
        load_tile(sb, xq, eq, rowBase, kc, 2, 2, tid);

        for (int kt = 0; kt < NKT; kt++) {
            asm volatile("cp.async.wait_group 2;" ::: "memory");
            __syncthreads();

            if (kt + 3 < NKT)
                load_tile(sb, xq, eq, rowBase, kc, kt + 3, (kt + 3) % NSTAGE, tid);

            const uint32_t aBase = sb + SA_OFF + (kt % NSTAGE) * 16384;
            const uint32_t bBase = sb + SB_OFF + (kt % NSTAGE) * 32768;
#pragma unroll
            for (int ks = 0; ks < 4; ks++) {      // 4 x k32 = BK 128
                uint32_t a[2][4], b[4][4];
#pragma unroll
                for (int mf = 0; mf < 2; mf++) {
                    int r = aRow0 + mf * 16;
                    int c = 2 * ks + aCsel;
                    uint32_t ad = aBase + r * 128 + (((uint32_t)(c ^ (r & 7))) << 4);
                    ldsm_x4(ad, a[mf][0], a[mf][1], a[mf][2], a[mf][3]);
                }
#pragma unroll
                for (int p = 0; p < 4; p++) {
                    int n = bRow0 + p * 16;
                    int c = 2 * ks + bCsel;
                    uint32_t bd = bBase + n * 128 + (((uint32_t)(c ^ (n & 7))) << 4);
                    ldsm_x4(bd, b[p][0], b[p][1], b[p][2], b[p][3]);
                }
#pragma unroll
                for (int mf = 0; mf < 2; mf++)
#pragma unroll
                    for (int p = 0; p < 4; p++) {
                        mma_s8(acc[mf][2 * p + 0], a[mf], b[p][0], b[p][1]);
                        mma_s8(acc[mf][2 * p + 1], a[mf], b[p][2], b[p][3]);
                    }
            }
        }
        asm volatile("cp.async.wait_group 0;" ::: "memory");

        // epilogue: fold scores into per-(thread,row-slot) top-4
        const float* sE = reinterpret_cast<const float*>(sm + SE_OFF);
#pragma unroll
        for (int mf = 0; mf < 2; mf++)
#pragma unroll
            for (int nf = 0; nf < 8; nf++)
#pragma unroll
                for (int e = 0; e < 4; e++) {
                    int col = warpN * 64 + nf * 8 + 2 * (lane & 3) + (e & 1);
                    float sc = fmaf(-prod, __int2float_rn(acc[mf][nf][e]), sE[col]);
                    int slot = mf * 2 + (e >> 1);
                    top4_insert(sc, kc * BN + col, tv[slot], ti4[slot]);
                }
        __syncthreads();   // guard sE before next kc overwrites
    }

    // final cross-thread merge (reuse tile smem region)
    float* cv = reinterpret_cast<float*>(sm);           // [128][16][4]
    int*   ci = reinterpret_cast<int*>(sm + 32768);     // [128][16][4]
    const int slice = warpN * 4 + (lane & 3);           // 16 col-slices
#pragma unroll
    for (int slot = 0; slot < 4; slot++) {
        int row = warpM * 32 + (slot >> 1) * 16 + (slot & 1) * 8 + (lane >> 2);
#pragma unroll
        for (int j = 0; j < 4; j++) {
            cv[(row * 16 + slice) * 4 + j] = tv[slot][j];
            ci[(row * 16 + slice) * 4 + j] = ti4[slot][j];
        }
    }
    __syncthreads();
    if (tid < BM) {
        float bv[4]; int bi[4];
#pragma unroll
        for (int j = 0; j < 4; j++) { bv[j] = 3.4e38f; bi[j] = 0x7fffffff; }
        for (int s = 0; s < 16; s++)
#pragma unroll
            for (int j = 0; j < 4; j++)
                top4_insert(cv[(tid * 16 + s) * 4 + j],
                            ci[(tid * 16 + s) * 4 + j], bv, bi);
        int row = rowBase + tid;
#pragma unroll
        for (int j = 0; j < 4; j++) {
            g_cand_v[row * 4 + j] = bv[j];
            g_cand_i[row * 4 + j] = bi[j];
        }
    }
}

// ---------------------------------------------------------------------------
// 4) fused exact rescore + gather/scatter (reference fp32 bit pattern)
// ---------------------------------------------------------------------------
__device__ __forceinline__ float exact_d(const float* __restrict__ xr,
                                         const float* __restrict__ er,
                                         float xx, float ee) {
    const float4* x4 = reinterpret_cast<const float4*>(xr);
    const float4* e4 = reinterpret_cast<const float4*>(er);
    float c = 0.f;
#pragma unroll 8
    for (int i = 0; i < D_DIM / 4; i++) {
        float4 a = x4[i], b = e4[i];
        c = __fmaf_rn(a.x, b.x, c);
        c = __fmaf_rn(a.y, b.y, c);
        c = __fmaf_rn(a.z, b.z, c);
        c = __fmaf_rn(a.w, b.w, c);
    }
    return __fadd_rn(__fsub_rn(xx, __fmul_rn(2.0f, c)), ee);
}

__global__ __launch_bounds__(128) void rescore_scatter_kernel(
    const float* __restrict__ x, const float* __restrict__ embed,
    float* __restrict__ out_ind, float* __restrict__ out_quant) {
    __shared__ float sv[128];
    __shared__ int   si[128];
    __shared__ int   sk;
    const int n = blockIdx.x;
    const int t = threadIdx.x;
    const float v0 = g_cand_v[n * 4 + 0];
    const float v3 = g_cand_v[n * 4 + 3];
    const float xx = g_xnorm[n];
    const float* xr = &x[(size_t)n * D_DIM];

    if (v3 > v0 + MARGIN) {
        // top-4 provably contains every code within margin of the approx min
        if (t < 4) {
            float vj = g_cand_v[n * 4 + t];
            int   kj = g_cand_i[n * 4 + t];
            if (vj <= v0 + MARGIN) {
                sv[t] = exact_d(xr, &embed[(size_t)kj * D_DIM], xx, g_enorm[kj]);
                si[t] = kj;
            } else { sv[t] = 3.4e38f; si[t] = 0x7fffffff; }
        }
        __syncthreads();
        if (t == 0) {
            float bv = sv[0]; int bi = si[0];
#pragma unroll
            for (int j = 1; j < 4; j++)
                if (sv[j] < bv || (sv[j] == bv && si[j] < bi)) { bv = sv[j]; bi = si[j]; }
            sk = bi; out_ind[n] = (float)bi;
        }
    } else {
        // fallback: exact full-row scan, 4 interleaved chains per thread
        float bv = 3.4e38f; int bi = 0x7fffffff;
        const float4* x4 = reinterpret_cast<const float4*>(xr);
        for (int i = 0; i < 32; i += 4) {
            int k0 = t + (i + 0) * 128, k1 = t + (i + 1) * 128;
            int k2 = t + (i + 2) * 128, k3 = t + (i + 3) * 128;
            const float4* e0 = reinterpret_cast<const float4*>(&embed[(size_t)k0 * D_DIM]);
            const float4* e1 = reinterpret_cast<const float4*>(&embed[(size_t)k1 * D_DIM]);
            const float4* e2 = reinterpret_cast<const float4*>(&embed[(size_t)k2 * D_DIM]);
            const float4* e3 = reinterpret_cast<const float4*>(&embed[(size_t)k3 * D_DIM]);
            float c0 = 0.f, c1 = 0.f, c2 = 0.f, c3 = 0.f;
#pragma unroll 4
            for (int dd = 0; dd < D_DIM / 4; dd++) {
                float4 a = x4[dd];
                float4 b0 = e0[dd], b1 = e1[dd], b2 = e2[dd], b3 = e3[dd];
                c0 = __fmaf_rn(a.x, b0.x, c0); c0 = __fmaf_rn(a.y, b0.y, c0);
                c0 = __fmaf_rn(a.z, b0.z, c0); c0 = __fmaf_rn(a.w, b0.w, c0);
                c1 = __fmaf_rn(a.x, b1.x, c1); c1 = __fmaf_rn(a.y, b1.y, c1);
                c1 = __fmaf_rn(a.z, b1.z, c1); c1 = __fmaf_rn(a.w, b1.w, c1);
                c2 = __fmaf_rn(a.x, b2.x, c2); c2 = __fmaf_rn(a.y, b2.y, c2);
                c2 = __fmaf_rn(a.z, b2.z, c2); c2 = __fmaf_rn(a.w, b2.w, c2);
                c3 = __fmaf_rn(a.x, b3.x, c3); c3 = __fmaf_rn(a.y, b3.y, c3);
                c3 = __fmaf_rn(a.z, b3.z, c3); c3 = __fmaf_rn(a.w, b3.w, c3);
            }
            float d0 = __fadd_rn(__fsub_rn(xx, __fmul_rn(2.0f, c0)), g_enorm[k0]);
            float d1 = __fadd_rn(__fsub_rn(xx, __fmul_rn(2.0f, c1)), g_enorm[k1]);
            float d2 = __fadd_rn(__fsub_rn(xx, __fmul_rn(2.0f, c2)), g_enorm[k2]);
            float d3 = __fadd_rn(__fsub_rn(xx, __fmul_rn(2.0f, c3)), g_enorm[k3]);
            if (d0 < bv || (d0 == bv && k0 < bi)) { bv = d0; bi = k0; }
            if (d1 < bv || (d1 == bv && k1 < bi)) { bv = d1; bi = k1; }
            if (d2 < bv || (d2 == bv && k2 < bi)) { bv = d2; bi = k2; }
            if (d3 < bv || (d3 == bv && k3 < bi)) { bv = d3; bi = k3; }
        }
        sv[t] = bv; si[t] = bi;
        __syncthreads();
        for (int s = 64; s > 0; s >>= 1) {
            if (t < s) {
                if (sv[t + s] < sv[t] || (sv[t + s] == sv[t] && si[t + s] < si[t])) {
                    sv[t] = sv[t + s]; si[t] = si[t + s];
                }
            }
            __syncthreads();
        }
        if (t == 0) { sk = si[0]; out_ind[n] = (float)si[0]; }
    }
    __syncthreads();

    // gather quantize + scatter EMA stats
    const int k = sk;
    float4 ev = *reinterpret_cast<const float4*>(&embed[(size_t)k * D_DIM + t * 4]);
    *reinterpret_cast<float4*>(&out_quant[(size_t)n * D_DIM + t * 4]) = ev;
    float4 xv = *reinterpret_cast<const float4*>(&x[(size_t)n * D_DIM + t * 4]);
    float* es = &g_embed_sum[(size_t)k * D_DIM + t * 4];
    atomicAdd(es + 0, xv.x);
    atomicAdd(es + 1, xv.y);
    atomicAdd(es + 2, xv.z);
    atomicAdd(es + 3, xv.w);
    if (t == 0) atomicAdd(&g_counts[k], 1.f);
}

// ---------------------------------------------------------------------------
// 5) EMA finalize
// ---------------------------------------------------------------------------
__global__ void finalize_cs(const float* __restrict__ cluster_size,
                            const float* __restrict__ decay_p,
                            float* __restrict__ out_ncs) {
    __shared__ float red[1024];
    int t = threadIdx.x;
    float decay = decay_p[0];
    float local = 0.f;
    for (int k = t; k < K_CODES; k += 1024) {
        float ncs = cluster_size[k] * decay + g_counts[k] * (1.f - decay);
        out_ncs[k] = ncs;
        local += ncs;
    }
    red[t] = local;
    __syncthreads();
    for (int s = 512; s > 0; s >>= 1) {
        if (t < s) red[t] += red[t + s];
        __syncthreads();
    }
    if (t == 0) g_total = red[0];
}

__global__ void finalize_embed(const float* __restrict__ cluster_size,
                               const float* __restrict__ embed_avg,
                               const float* __restrict__ decay_p,
                               float* __restrict__ out_nea,
                               float* __restrict__ out_ne) {
    int k = blockIdx.x;
    int t = threadIdx.x;
    float decay = decay_p[0];
    float omd   = 1.f - decay;
    float ncs   = cluster_size[k] * decay + g_counts[k] * omd;
    float total = g_total;
    float smoothed = (ncs + EPSF) / (total + EPSF * (float)K_CODES) * total;
    size_t base = (size_t)k * D_DIM + t * 4;
    float4 ea = *reinterpret_cast<const float4*>(&embed_avg[base]);
    float4 es = *reinterpret_cast<const float4*>(&g_embed_sum[base]);
    float4 nea;
    nea.x = ea.x * decay + es.x * omd;
    nea.y = ea.y * decay + es.y * omd;
    nea.z = ea.z * decay + es.z * omd;
    nea.w = ea.w * decay + es.w * omd;
    *reinterpret_cast<float4*>(&out_nea[base]) = nea;
    float4 ne;
    ne.x = nea.x / smoothed; ne.y = nea.y / smoothed;
    ne.z = nea.z / smoothed; ne.w = nea.w / smoothed;
    *reinterpret_cast<float4*>(&out_ne[base]) = ne;
}

// ---------------------------------------------------------------------------
extern "C" void kernel_launch(void* const* d_in, const int* in_sizes, int n_in,
                              void* d_out, int out_size) {
    const float* x            = (const float*)d_in[0];
    const float* embed        = (const float*)d_in[1];
    const float* cluster_size = (const float*)d_in[2];
    const float* embed_avg    = (const float*)d_in[3];
    const float* decay        = (const float*)d_in[4];

    float* out     = (float*)d_out;
    float* out_q   = out;
    float* out_ind = out_q   + (size_t)N_ROWS * D_DIM;
    float* out_ncs = out_ind + N_ROWS;
    float* out_nea = out_ncs + K_CODES;
    float* out_ne  = out_nea + (size_t)K_CODES * D_DIM;

    static int smem_set = 0;
    if (!smem_set) {
        cudaFuncSetAttribute(gemm_topk_kernel,
                             cudaFuncAttributeMaxDynamicSharedMemorySize, SMEMSZ);
        smem_set = 1;
    }

    int8_t *xq, *eq;
    cudaGetSymbolAddress((void**)&xq, g_xq);
    cudaGetSymbolAddress((void**)&eq, g_eq);

    zero_kernel<<<2048, 256>>>();
    enorm_kernel<<<K_CODES / 256, 256>>>(embed);
    xnorm_kernel<<<N_ROWS / 256, 256>>>(x);
    maxabs_kernel<<<1024, 256>>>(x, N_ROWS * D_DIM / 4, 0);
    maxabs_kernel<<<256, 256>>>(embed, K_CODES * D_DIM / 4, 1);
    scale_kernel<<<1, 1>>>();
    quant_kernel<<<(N_ROWS * D_DIM / 4) / 256, 256>>>(x, xq, N_ROWS * D_DIM / 4, 0);
    quant_kernel<<<(K_CODES * D_DIM / 4) / 256, 256>>>(embed, eq, K_CODES * D_DIM / 4, 1);
    gemm_topk_kernel<<<N_ROWS / BM, 512, SMEMSZ>>>(xq, eq);
    rescore_scatter_kernel<<<N_ROWS, 128>>>(x, embed, out_ind, out_q);
    finalize_cs<<<1, 1024>>>(cluster_size, decay, out_ncs);
    finalize_embed<<<K_CODES, 128>>>(cluster_size, embed_avg, decay,
                                     out_nea, out_ne);
}

// round 15
// speedup vs baseline: 5.2295x; 5.2295x over previous
#include <cuda_runtime.h>
#include <cuda_bf16.h>
#include <cstdint>

#define N_ROWS  32768
#define D_DIM   512
#define K_CODES 4096
#define EPSF    1e-6f
#define MARGIN  0.03f

// ---- GEMM tiling (R12-proven bf16 shape, flattened pipeline) ----
#define BM 128
#define BN 256
#define BK 64                 // bf16: 64 elems = 128B
#define NKT (D_DIM / BK)      // 8 depth tiles
#define NKC (K_CODES / BN)    // 16 code chunks
#define NTILE (NKC * NKT)     // 128 flattened tiles
#define NSTAGE 4

// smem layout (dynamic): A 4x16KB | B 4x32KB | enorm 16KB (all K)
#define SA_OFF 0
#define SB_OFF 65536
#define SE_OFF 196608
#define SMEMSZ 212992

// ---- scratch (static, no allocations) ----
__device__ __align__(16) __nv_bfloat16 g_xb[N_ROWS * D_DIM];
__device__ __align__(16) __nv_bfloat16 g_eb[K_CODES * D_DIM];
__device__ float g_enorm[K_CODES];
__device__ float g_xnorm[N_ROWS];
__device__ float g_cand_v[N_ROWS * 4];
__device__ int   g_cand_i[N_ROWS * 4];
__device__ float g_embed_sum[K_CODES * D_DIM];
__device__ float g_counts[K_CODES];
__device__ float g_total;

// ---------------------------------------------------------------------------
// helpers
// ---------------------------------------------------------------------------
__device__ __forceinline__ uint32_t smem_u32(const void* p) {
    uint32_t a;
    asm("{ .reg .u64 t; cvta.to.shared.u64 t, %1; cvt.u32.u64 %0, t; }"
        : "=r"(a) : "l"(p));
    return a;
}

__device__ __forceinline__ void ldsm_x4(uint32_t a, uint32_t& r0, uint32_t& r1,
                                        uint32_t& r2, uint32_t& r3) {
    asm volatile("ldmatrix.sync.aligned.m8n8.x4.shared.b16 {%0,%1,%2,%3}, [%4];"
                 : "=r"(r0), "=r"(r1), "=r"(r2), "=r"(r3) : "r"(a));
}

__device__ __forceinline__ void mma_bf16(float* c, const uint32_t* a,
                                         uint32_t b0, uint32_t b1) {
    asm volatile(
        "mma.sync.aligned.m16n8k16.row.col.f32.bf16.bf16.f32 "
        "{%0,%1,%2,%3}, {%4,%5,%6,%7}, {%8,%9}, {%0,%1,%2,%3};"
        : "+f"(c[0]), "+f"(c[1]), "+f"(c[2]), "+f"(c[3])
        : "r"(a[0]), "r"(a[1]), "r"(a[2]), "r"(a[3]), "r"(b0), "r"(b1));
}

__device__ __forceinline__ void top4_insert(float s, int k, float v[4], int id[4]) {
    if (s < v[3]) {
        if (s < v[1]) {
            v[3] = v[2]; id[3] = id[2]; v[2] = v[1]; id[2] = id[1];
            if (s < v[0]) { v[1] = v[0]; id[1] = id[0]; v[0] = s; id[0] = k; }
            else          { v[1] = s; id[1] = k; }
        } else {
            if (s < v[2]) { v[3] = v[2]; id[3] = id[2]; v[2] = s; id[2] = k; }
            else          { v[3] = s; id[3] = k; }
        }
    }
}

// ---------------------------------------------------------------------------
// 0) zero scratch
// ---------------------------------------------------------------------------
__global__ void zero_kernel() {
    int i = blockIdx.x * blockDim.x + threadIdx.x;
    int stride = gridDim.x * blockDim.x;
    for (int j = i; j < K_CODES * D_DIM; j += stride) g_embed_sum[j] = 0.f;
    if (i < K_CODES) g_counts[i] = 0.f;
    if (i == 0) g_total = 0.f;
}

// ---------------------------------------------------------------------------
// 1) exact norms, reference rounding order (sequential mul/add)
// ---------------------------------------------------------------------------
__global__ void enorm_kernel(const float* __restrict__ embed) {
    int k = blockIdx.x * blockDim.x + threadIdx.x;
    if (k >= K_CODES) return;
    const float4* row = reinterpret_cast<const float4*>(&embed[(size_t)k * D_DIM]);
    float s = 0.f;
#pragma unroll 8
    for (int i = 0; i < D_DIM / 4; i++) {
        float4 v = row[i];
        s = __fadd_rn(s, __fmul_rn(v.x, v.x));
        s = __fadd_rn(s, __fmul_rn(v.y, v.y));
        s = __fadd_rn(s, __fmul_rn(v.z, v.z));
        s = __fadd_rn(s, __fmul_rn(v.w, v.w));
    }
    g_enorm[k] = s;
}
__global__ void xnorm_kernel(const float* __restrict__ x) {
    int n = blockIdx.x * blockDim.x + threadIdx.x;
    if (n >= N_ROWS) return;
    const float4* row = reinterpret_cast<const float4*>(&x[(size_t)n * D_DIM]);
    float s = 0.f;
#pragma unroll 8
    for (int i = 0; i < D_DIM / 4; i++) {
        float4 v = row[i];
        s = __fadd_rn(s, __fmul_rn(v.x, v.x));
        s = __fadd_rn(s, __fmul_rn(v.y, v.y));
        s = __fadd_rn(s, __fmul_rn(v.z, v.z));
        s = __fadd_rn(s, __fmul_rn(v.w, v.w));
    }
    g_xnorm[n] = s;
}

// ---------------------------------------------------------------------------
// 2) bf16 conversion pass
// ---------------------------------------------------------------------------
__global__ void bf16_kernel(const float* __restrict__ src,
                            __nv_bfloat16* __restrict__ dst, int n4) {
    int i = blockIdx.x * blockDim.x + threadIdx.x;
    if (i >= n4) return;
    float4 v = reinterpret_cast<const float4*>(src)[i];
    __nv_bfloat162* dp = reinterpret_cast<__nv_bfloat162*>(dst + (size_t)i * 4);
    dp[0] = __nv_bfloat162(__float2bfloat16(v.x), __float2bfloat16(v.y));
    dp[1] = __nv_bfloat162(__float2bfloat16(v.z), __float2bfloat16(v.w));
}

// ---------------------------------------------------------------------------
// 3) bf16 mma.sync GEMM, flattened continuous pipeline + per-row top-4
//    score(n,k) = enorm_k - 2 * <x_n, e_k>
// ---------------------------------------------------------------------------
__device__ __forceinline__ void load_tile(uint32_t sb,
                                          const __nv_bfloat16* __restrict__ xb,
                                          const __nv_bfloat16* __restrict__ eb,
                                          int rowBase, int g, int tid) {
    const int kc = g >> 3, kt = g & 7, stage = g & 3;
    const uint32_t aOff = sb + SA_OFF + stage * 16384;
    const uint32_t bOff = sb + SB_OFF + stage * 32768;
    // A: 128 rows x 8 16B-chunks = 1024 transfers (2/thread)
#pragma unroll
    for (int i = 0; i < 2; i++) {
        int idx = tid + i * 512;
        int r = idx >> 3, c = idx & 7;
        uint32_t sw = (uint32_t)(r * 128 + ((c ^ (r & 7)) << 4));
        const __nv_bfloat16* ga = xb + (size_t)(rowBase + r) * D_DIM + kt * BK + c * 8;
        asm volatile("cp.async.cg.shared.global [%0], [%1], 16;"
                     :: "r"(aOff + sw), "l"(ga));
    }
    // B: 256 rows x 8 16B-chunks = 2048 transfers (4/thread)
#pragma unroll
    for (int i = 0; i < 4; i++) {
        int idx = tid + i * 512;
        int r = idx >> 3, c = idx & 7;
        uint32_t sw = (uint32_t)(r * 128 + ((c ^ (r & 7)) << 4));
        const __nv_bfloat16* gb = eb + (size_t)(kc * BN + r) * D_DIM + kt * BK + c * 8;
        asm volatile("cp.async.cg.shared.global [%0], [%1], 16;"
                     :: "r"(bOff + sw), "l"(gb));
    }
    asm volatile("cp.async.commit_group;" ::: "memory");
}

__global__ __launch_bounds__(512, 1) void gemm_topk_kernel(
    const __nv_bfloat16* __restrict__ xb, const __nv_bfloat16* __restrict__ eb) {
    extern __shared__ char sm[];
    const uint32_t sb = smem_u32(sm);
    const int tid = threadIdx.x, lane = tid & 31, wid = tid >> 5;
    const int warpM = wid & 3;           // 4 row-groups of 32
    const int warpN = wid >> 2;          // 4 col-quarters of 64
    const int rowBase = blockIdx.x * BM;

    // preload full enorm (4096 floats) into smem once
    {
        float4* se4 = reinterpret_cast<float4*>(sm + SE_OFF);
        const float4* ge4 = reinterpret_cast<const float4*>(g_enorm);
        se4[tid]       = ge4[tid];
        se4[tid + 512] = ge4[tid + 512];
    }

    float tv[4][4]; int ti4[4][4];
#pragma unroll
    for (int s = 0; s < 4; s++)
#pragma unroll
        for (int j = 0; j < 4; j++) { tv[s][j] = 3.4e38f; ti4[s][j] = 0x7fffffff; }

    // ldmatrix address components (canonical m16n8k16 mapping)
    const int aRow0 = warpM * 32 + (lane & 15);
    const int aCsel = lane >> 4;
    const int bRow0 = warpN * 64 + ((lane >> 4) << 3) + (lane & 7);
    const int bCsel = (lane >> 3) & 1;

    float acc[2][8][4];
#pragma unroll
    for (int mf = 0; mf < 2; mf++)
#pragma unroll
        for (int nf = 0; nf < 8; nf++)
#pragma unroll
            for (int e = 0; e < 4; e++) acc[mf][nf][e] = 0.f;

    load_tile(sb, xb, eb, rowBase, 0, tid);
    load_tile(sb, xb, eb, rowBase, 1, tid);
    load_tile(sb, xb, eb, rowBase, 2, tid);

    const float* sE = reinterpret_cast<const float*>(sm + SE_OFF);

    for (int g = 0; g < NTILE; g++) {
        asm volatile("cp.async.wait_group 2;" ::: "memory");
        __syncthreads();   // stage g ready; stage (g+3)%4 fully consumed

        if (g + 3 < NTILE)
            load_tile(sb, xb, eb, rowBase, g + 3, tid);

        const uint32_t aBase = sb + SA_OFF + (g & 3) * 16384;
        const uint32_t bBase = sb + SB_OFF + (g & 3) * 32768;
#pragma unroll
        for (int ks = 0; ks < 4; ks++) {      // 4 x k16 = BK 64
            uint32_t a[2][4], b[4][4];
#pragma unroll
            for (int mf = 0; mf < 2; mf++) {
                int r = aRow0 + mf * 16;
                int c = 2 * ks + aCsel;
                uint32_t ad = aBase + r * 128 + (((uint32_t)(c ^ (r & 7))) << 4);
                ldsm_x4(ad, a[mf][0], a[mf][1], a[mf][2], a[mf][3]);
            }
#pragma unroll
            for (int p = 0; p < 4; p++) {
                int n = bRow0 + p * 16;
                int c = 2 * ks + bCsel;
                uint32_t bd = bBase + n * 128 + (((uint32_t)(c ^ (n & 7))) << 4);
                ldsm_x4(bd, b[p][0], b[p][1], b[p][2], b[p][3]);
            }
#pragma unroll
            for (int mf = 0; mf < 2; mf++)
#pragma unroll
                for (int p = 0; p < 4; p++) {
                    mma_bf16(acc[mf][2 * p + 0], a[mf], b[p][0], b[p][1]);
                    mma_bf16(acc[mf][2 * p + 1], a[mf], b[p][2], b[p][3]);
                }
        }

        // kc-chunk complete: fold scores (registers + static sE only, no sync)
        if ((g & 7) == 7) {
            const int kc = g >> 3;
#pragma unroll
            for (int mf = 0; mf < 2; mf++)
#pragma unroll
                for (int nf = 0; nf < 8; nf++)
#pragma unroll
                    for (int e = 0; e < 4; e++) {
                        int col = warpN * 64 + nf * 8 + 2 * (lane & 3) + (e & 1);
                        float sc = fmaf(-2.f, acc[mf][nf][e], sE[kc * BN + col]);
                        int slot = mf * 2 + (e >> 1);
                        top4_insert(sc, kc * BN + col, tv[slot], ti4[slot]);
                        acc[mf][nf][e] = 0.f;
                    }
        }
    }
    asm volatile("cp.async.wait_group 0;" ::: "memory");
    __syncthreads();   // all tile traffic done before smem reuse

    // final cross-thread merge (reuse tile smem region)
    float* cv = reinterpret_cast<float*>(sm);           // [128][16][4]
    int*   ci = reinterpret_cast<int*>(sm + 32768);     // [128][16][4]
    const int slice = warpN * 4 + (lane & 3);           // 16 col-slices
#pragma unroll
    for (int slot = 0; slot < 4; slot++) {
        int row = warpM * 32 + (slot >> 1) * 16 + (slot & 1) * 8 + (lane >> 2);
#pragma unroll
        for (int j = 0; j < 4; j++) {
            cv[(row * 16 + slice) * 4 + j] = tv[slot][j];
            ci[(row * 16 + slice) * 4 + j] = ti4[slot][j];
        }
    }
    __syncthreads();
    if (tid < BM) {
        float bv[4]; int bi[4];
#pragma unroll
        for (int j = 0; j < 4; j++) { bv[j] = 3.4e38f; bi[j] = 0x7fffffff; }
        for (int s = 0; s < 16; s++)
#pragma unroll
            for (int j = 0; j < 4; j++)
                top4_insert(cv[(tid * 16 + s) * 4 + j],
                            ci[(tid * 16 + s) * 4 + j], bv, bi);
        int row = rowBase + tid;
#pragma unroll
        for (int j = 0; j < 4; j++) {
            g_cand_v[row * 4 + j] = bv[j];
            g_cand_i[row * 4 + j] = bi[j];
        }
    }
}

// ---------------------------------------------------------------------------
// 4) fused exact rescore + gather/scatter (reference fp32 bit pattern)
// ---------------------------------------------------------------------------
__device__ __forceinline__ float exact_d(const float* __restrict__ xr,
                                         const float* __restrict__ er,
                                         float xx, float ee) {
    const float4* x4 = reinterpret_cast<const float4*>(xr);
    const float4* e4 = reinterpret_cast<const float4*>(er);
    float c = 0.f;
#pragma unroll 8
    for (int i = 0; i < D_DIM / 4; i++) {
        float4 a = x4[i], b = e4[i];
        c = __fmaf_rn(a.x, b.x, c);
        c = __fmaf_rn(a.y, b.y, c);
        c = __fmaf_rn(a.z, b.z, c);
        c = __fmaf_rn(a.w, b.w, c);
    }
    return __fadd_rn(__fsub_rn(xx, __fmul_rn(2.0f, c)), ee);
}

__global__ __launch_bounds__(128) void rescore_scatter_kernel(
    const float* __restrict__ x, const float* __restrict__ embed,
    float* __restrict__ out_ind, float* __restrict__ out_quant) {
    __shared__ float sv[128];
    __shared__ int   si[128];
    __shared__ int   sk;
    const int n = blockIdx.x;
    const int t = threadIdx.x;
    const float v0 = g_cand_v[n * 4 + 0];
    const float v3 = g_cand_v[n * 4 + 3];
    const float xx = g_xnorm[n];
    const float* xr = &x[(size_t)n * D_DIM];

    if (v3 > v0 + MARGIN) {
        // top-4 provably contains every code within margin of the approx min
        if (t < 4) {
            float vj = g_cand_v[n * 4 + t];
            int   kj = g_cand_i[n * 4 + t];
            if (vj <= v0 + MARGIN) {
                sv[t] = exact_d(xr, &embed[(size_t)kj * D_DIM], xx, g_enorm[kj]);
                si[t] = kj;
            } else { sv[t] = 3.4e38f; si[t] = 0x7fffffff; }
        }
        __syncthreads();
        if (t == 0) {
            float bv = sv[0]; int bi = si[0];
#pragma unroll
            for (int j = 1; j < 4; j++)
                if (sv[j] < bv || (sv[j] == bv && si[j] < bi)) { bv = sv[j]; bi = si[j]; }
            sk = bi; out_ind[n] = (float)bi;
        }
    } else {
        // rare fallback: exact full-row scan, 4 interleaved chains per thread
        float bv = 3.4e38f; int bi = 0x7fffffff;
        const float4* x4 = reinterpret_cast<const float4*>(xr);
        for (int i = 0; i < 32; i += 4) {
            int k0 = t + (i + 0) * 128, k1 = t + (i + 1) * 128;
            int k2 = t + (i + 2) * 128, k3 = t + (i + 3) * 128;
            const float4* e0 = reinterpret_cast<const float4*>(&embed[(size_t)k0 * D_DIM]);
            const float4* e1 = reinterpret_cast<const float4*>(&embed[(size_t)k1 * D_DIM]);
            const float4* e2 = reinterpret_cast<const float4*>(&embed[(size_t)k2 * D_DIM]);
            const float4* e3 = reinterpret_cast<const float4*>(&embed[(size_t)k3 * D_DIM]);
            float c0 = 0.f, c1 = 0.f, c2 = 0.f, c3 = 0.f;
#pragma unroll 4
            for (int dd = 0; dd < D_DIM / 4; dd++) {
                float4 a = x4[dd];
                float4 b0 = e0[dd], b1 = e1[dd], b2 = e2[dd], b3 = e3[dd];
                c0 = __fmaf_rn(a.x, b0.x, c0); c0 = __fmaf_rn(a.y, b0.y, c0);
                c0 = __fmaf_rn(a.z, b0.z, c0); c0 = __fmaf_rn(a.w, b0.w, c0);
                c1 = __fmaf_rn(a.x, b1.x, c1); c1 = __fmaf_rn(a.y, b1.y, c1);
                c1 = __fmaf_rn(a.z, b1.z, c1); c1 = __fmaf_rn(a.w, b1.w, c1);
                c2 = __fmaf_rn(a.x, b2.x, c2); c2 = __fmaf_rn(a.y, b2.y, c2);
                c2 = __fmaf_rn(a.z, b2.z, c2); c2 = __fmaf_rn(a.w, b2.w, c2);
                c3 = __fmaf_rn(a.x, b3.x, c3); c3 = __fmaf_rn(a.y, b3.y, c3);
                c3 = __fmaf_rn(a.z, b3.z, c3); c3 = __fmaf_rn(a.w, b3.w, c3);
            }
            float d0 = __fadd_rn(__fsub_rn(xx, __fmul_rn(2.0f, c0)), g_enorm[k0]);
            float d1 = __fadd_rn(__fsub_rn(xx, __fmul_rn(2.0f, c1)), g_enorm[k1]);
            float d2 = __fadd_rn(__fsub_rn(xx, __fmul_rn(2.0f, c2)), g_enorm[k2]);
            float d3 = __fadd_rn(__fsub_rn(xx, __fmul_rn(2.0f, c3)), g_enorm[k3]);
            if (d0 < bv || (d0 == bv && k0 < bi)) { bv = d0; bi = k0; }
            if (d1 < bv || (d1 == bv && k1 < bi)) { bv = d1; bi = k1; }
            if (d2 < bv || (d2 == bv && k2 < bi)) { bv = d2; bi = k2; }
            if (d3 < bv || (d3 == bv && k3 < bi)) { bv = d3; bi = k3; }
        }
        sv[t] = bv; si[t] = bi;
        __syncthreads();
        for (int s = 64; s > 0; s >>= 1) {
            if (t < s) {
                if (sv[t + s] < sv[t] || (sv[t + s] == sv[t] && si[t + s] < si[t])) {
                    sv[t] = sv[t + s]; si[t] = si[t + s];
                }
            }
            __syncthreads();
        }
        if (t == 0) { sk = si[0]; out_ind[n] = (float)si[0]; }
    }
    __syncthreads();

    // gather quantize + scatter EMA stats
    const int k = sk;
    float4 ev = *reinterpret_cast<const float4*>(&embed[(size_t)k * D_DIM + t * 4]);
    *reinterpret_cast<float4*>(&out_quant[(size_t)n * D_DIM + t * 4]) = ev;
    float4 xv = *reinterpret_cast<const float4*>(&x[(size_t)n * D_DIM + t * 4]);
    float* es = &g_embed_sum[(size_t)k * D_DIM + t * 4];
    atomicAdd(es + 0, xv.x);
    atomicAdd(es + 1, xv.y);
    atomicAdd(es + 2, xv.z);
    atomicAdd(es + 3, xv.w);
    if (t == 0) atomicAdd(&g_counts[k], 1.f);
}

// ---------------------------------------------------------------------------
// 5) EMA finalize
// ---------------------------------------------------------------------------
__global__ void finalize_cs(const float* __restrict__ cluster_size,
                            const float* __restrict__ decay_p,
                            float* __restrict__ out_ncs) {
    __shared__ float red[1024];
    int t = threadIdx.x;
    float decay = decay_p[0];
    float local = 0.f;
    for (int k = t; k < K_CODES; k += 1024) {
        float ncs = cluster_size[k] * decay + g_counts[k] * (1.f - decay);
        out_ncs[k] = ncs;
        local += ncs;
    }
    red[t] = local;
    __syncthreads();
    for (int s = 512; s > 0; s >>= 1) {
        if (t < s) red[t] += red[t + s];
        __syncthreads();
    }
    if (t == 0) g_total = red[0];
}

__global__ void finalize_embed(const float* __restrict__ cluster_size,
                               const float* __restrict__ embed_avg,
                               const float* __restrict__ decay_p,
                               float* __restrict__ out_nea,
                               float* __restrict__ out_ne) {
    int k = blockIdx.x;
    int t = threadIdx.x;
    float decay = decay_p[0];
    float omd   = 1.f - decay;
    float ncs   = cluster_size[k] * decay + g_counts[k] * omd;
    float total = g_total;
    float smoothed = (ncs + EPSF) / (total + EPSF * (float)K_CODES) * total;
    size_t base = (size_t)k * D_DIM + t * 4;
    float4 ea = *reinterpret_cast<const float4*>(&embed_avg[base]);
    float4 es = *reinterpret_cast<const float4*>(&g_embed_sum[base]);
    float4 nea;
    nea.x = ea.x * decay + es.x * omd;
    nea.y = ea.y * decay + es.y * omd;
    nea.z = ea.z * decay + es.z * omd;
    nea.w = ea.w * decay + es.w * omd;
    *reinterpret_cast<float4*>(&out_nea[base]) = nea;
    float4 ne;
    ne.x = nea.x / smoothed; ne.y = nea.y / smoothed;
    ne.z = nea.z / smoothed; ne.w = nea.w / smoothed;
    *reinterpret_cast<float4*>(&out_ne[base]) = ne;
}

// ---------------------------------------------------------------------------
extern "C" void kernel_launch(void* const* d_in, const int* in_sizes, int n_in,
                              void* d_out, int out_size) {
    const float* x            = (const float*)d_in[0];
    const float* embed        = (const float*)d_in[1];
    const float* cluster_size = (const float*)d_in[2];
    const float* embed_avg    = (const float*)d_in[3];
    const float* decay        = (const float*)d_in[4];

    float* out     = (float*)d_out;
    float* out_q   = out;
    float* out_ind = out_q   + (size_t)N_ROWS * D_DIM;
    float* out_ncs = out_ind + N_ROWS;
    float* out_nea = out_ncs + K_CODES;
    float* out_ne  = out_nea + (size_t)K_CODES * D_DIM;

    static int smem_set = 0;
    if (!smem_set) {
        cudaFuncSetAttribute(gemm_topk_kernel,
                             cudaFuncAttributeMaxDynamicSharedMemorySize, SMEMSZ);
        smem_set = 1;
    }

    __nv_bfloat16 *xb, *eb;
    cudaGetSymbolAddress((void**)&xb, g_xb);
    cudaGetSymbolAddress((void**)&eb, g_eb);

    zero_kernel<<<2048, 256>>>();
    enorm_kernel<<<K_CODES / 256, 256>>>(embed);
    xnorm_kernel<<<N_ROWS / 256, 256>>>(x);
    bf16_kernel<<<(N_ROWS * D_DIM / 4) / 256, 256>>>(x, xb, N_ROWS * D_DIM / 4);
    bf16_kernel<<<(K_CODES * D_DIM / 4) / 256, 256>>>(embed, eb, K_CODES * D_DIM / 4);
    gemm_topk_kernel<<<N_ROWS / BM, 512, SMEMSZ>>>(xb, eb);
    rescore_scatter_kernel<<<N_ROWS, 128>>>(x, embed, out_ind, out_q);
    finalize_cs<<<1, 1024>>>(cluster_size, decay, out_ncs);
    finalize_embed<<<K_CODES, 128>>>(cluster_size, embed_avg, decay,
                                     out_nea, out_ne);
}